// round 8
// baseline (speedup 1.0000x reference)
#include <cuda_runtime.h>

// TAHE: masked cosine-similarity weighted pooling.
// out[b,d] = sum_l [ts[b,l]>0] * (dot(cur_n[b], rec_n[b,l]) + 1)/2 * emb[b,l,d]
//
// R8: explicit 2-stage software pipeline (2 rows/stage). Next pair's rec
//     loads + current pair's emb loads are issued BEFORE the shuffle chain,
//     so memory is in flight during the ~160-cycle reduction every iter.
//     __launch_bounds__(256,6) gives ptxas a 42-reg budget so the pipeline
//     registers stay live (R6 showed regs=32 kills front-batching).

#define TAHE_B 4096
#define TAHE_L 200
#define TAHE_D 128
#define WARPS_PER_CTA 8
#define ROWS_PER_CTA  4        // batch rows per CTA (2 warps each)
#define L_HALF        100      // L per warp

__global__ __launch_bounds__(WARPS_PER_CTA * 32, 6)
void tahe_kernel(const float* __restrict__ rec,
                 const float* __restrict__ cur,
                 const int*   __restrict__ ts,
                 const float* __restrict__ emb,
                 float*       __restrict__ out) {
    __shared__ short s_list[WARPS_PER_CTA][L_HALF + 8];
    __shared__ float s_part[ROWS_PER_CTA][TAHE_D];   // partials from half==1 warps

    const int warp = threadIdx.x >> 5;
    const int lane = threadIdx.x & 31;
    const int row  = warp >> 1;              // 0..3 within CTA
    const int half = warp & 1;               // which L half
    const int b    = blockIdx.x * ROWS_PER_CTA + row;

    const unsigned lanemask_lt = (1u << lane) - 1u;

    // ---- normalize current representation (lane owns 4 contiguous floats) ----
    float4 c = reinterpret_cast<const float4*>(cur + (size_t)b * TAHE_D)[lane];
    float csq = c.x * c.x + c.y * c.y + c.z * c.z + c.w * c.w;
    #pragma unroll
    for (int o = 16; o > 0; o >>= 1)
        csq += __shfl_xor_sync(0xFFFFFFFFu, csq, o);
    const float cinv = rsqrtf(fmaxf(csq, 1e-12f));
    c.x *= cinv; c.y *= cinv; c.z *= cinv; c.w *= cinv;

    // ---- compact active l indices for this warp's L-half into smem ----
    const int* tsb = ts + (size_t)b * TAHE_L + half * L_HALF;
    int cnt = 0;
    #pragma unroll
    for (int chunk = 0; chunk < 4; chunk++) {           // 4*32 = 128 >= 100
        const int li = chunk * 32 + lane;
        const int t  = (li < L_HALF) ? tsb[li] : 0;
        const unsigned ballot = __ballot_sync(0xFFFFFFFFu, t > 0);
        if (t > 0)
            s_list[warp][cnt + __popc(ballot & lanemask_lt)] =
                (short)(half * L_HALF + li);
        cnt += __popc(ballot);
    }
    __syncwarp();

    const float4* recb = reinterpret_cast<const float4*>(rec + (size_t)b * TAHE_L * TAHE_D);
    const float4* embb = reinterpret_cast<const float4*>(emb + (size_t)b * TAHE_L * TAHE_D);

    float4 acc = make_float4(0.f, 0.f, 0.f, 0.f);

    // ---- pipelined main loop: 2 rows per stage ----
    int i = 0;
    if (cnt >= 2) {
        int cl0 = s_list[warp][0];
        int cl1 = s_list[warp][1];
        float4 ra = recb[(size_t)cl0 * 32 + lane];
        float4 rb = recb[(size_t)cl1 * 32 + lane];

        for (;;) {
            // partials from current rec pair (frees ra/rb registers)
            float d0 = ra.x*c.x + ra.y*c.y + ra.z*c.z + ra.w*c.w;
            float s0 = ra.x*ra.x + ra.y*ra.y + ra.z*ra.z + ra.w*ra.w;
            float d1 = rb.x*c.x + rb.y*c.y + rb.z*c.z + rb.w*c.w;
            float s1 = rb.x*rb.x + rb.y*rb.y + rb.z*rb.z + rb.w*rb.w;

            // issue emb loads for the current pair (consumed after shuffles)
            const float4 e0 = embb[(size_t)cl0 * 32 + lane];
            const float4 e1 = embb[(size_t)cl1 * 32 + lane];

            // issue rec prefetch for the next pair (consumed next iteration)
            i += 2;
            const bool more = (i + 2 <= cnt);
            const int n0 = more ? (int)s_list[warp][i]     : 0;
            const int n1 = more ? (int)s_list[warp][i + 1] : 0;
            ra = recb[(size_t)n0 * 32 + lane];
            rb = recb[(size_t)n1 * 32 + lane];

            // shuffle reduction (loads above in flight during this chain)
            #pragma unroll
            for (int o = 16; o > 0; o >>= 1) {
                d0 += __shfl_xor_sync(0xFFFFFFFFu, d0, o);
                s0 += __shfl_xor_sync(0xFFFFFFFFu, s0, o);
                d1 += __shfl_xor_sync(0xFFFFFFFFu, d1, o);
                s1 += __shfl_xor_sync(0xFFFFFFFFu, s1, o);
            }

            const float w0 = (d0 * rsqrtf(fmaxf(s0, 1e-12f)) + 1.0f) * 0.5f;
            const float w1 = (d1 * rsqrtf(fmaxf(s1, 1e-12f)) + 1.0f) * 0.5f;

            acc.x = fmaf(w0, e0.x, fmaf(w1, e1.x, acc.x));
            acc.y = fmaf(w0, e0.y, fmaf(w1, e1.y, acc.y));
            acc.z = fmaf(w0, e0.z, fmaf(w1, e1.z, acc.z));
            acc.w = fmaf(w0, e0.w, fmaf(w1, e1.w, acc.w));

            if (!more) break;
            cl0 = n0; cl1 = n1;
        }
    }
    // ---- odd tail (at most one row) ----
    if (cnt & 1) {
        const int la = s_list[warp][cnt - 1];
        const float4 r0 = recb[(size_t)la * 32 + lane];
        const float4 e0 = embb[(size_t)la * 32 + lane];
        float d0 = r0.x*c.x + r0.y*c.y + r0.z*c.z + r0.w*c.w;
        float s0 = r0.x*r0.x + r0.y*r0.y + r0.z*r0.z + r0.w*r0.w;
        #pragma unroll
        for (int o = 16; o > 0; o >>= 1) {
            d0 += __shfl_xor_sync(0xFFFFFFFFu, d0, o);
            s0 += __shfl_xor_sync(0xFFFFFFFFu, s0, o);
        }
        const float w0 = (d0 * rsqrtf(fmaxf(s0, 1e-12f)) + 1.0f) * 0.5f;
        acc.x = fmaf(w0, e0.x, acc.x);
        acc.y = fmaf(w0, e0.y, acc.y);
        acc.z = fmaf(w0, e0.z, acc.z);
        acc.w = fmaf(w0, e0.w, acc.w);
    }

    // ---- combine the two half-warps ----
    if (half == 1)
        reinterpret_cast<float4*>(s_part[row])[lane] = acc;
    __syncthreads();
    if (half == 0) {
        const float4 p = reinterpret_cast<const float4*>(s_part[row])[lane];
        acc.x += p.x; acc.y += p.y; acc.z += p.z; acc.w += p.w;
        reinterpret_cast<float4*>(out + (size_t)b * TAHE_D)[lane] = acc;
    }
}

extern "C" void kernel_launch(void* const* d_in, const int* in_sizes, int n_in,
                              void* d_out, int out_size) {
    const float* rec = (const float*)d_in[0];
    const float* cur = (const float*)d_in[1];
    const int*   ts  = (const int*)  d_in[2];
    const float* emb = (const float*)d_in[3];
    float*       out = (float*)d_out;

    const int ctas = TAHE_B / ROWS_PER_CTA;  // 1024
    tahe_kernel<<<ctas, WARPS_PER_CTA * 32>>>(rec, cur, ts, emb, out);
}

// round 9
// speedup vs baseline: 1.0364x; 1.0364x over previous
#include <cuda_runtime.h>

// TAHE: masked cosine-similarity weighted pooling.
// out[b,d] = sum_l [ts[b,l]>0] * (dot(cur_n[b], rec_n[b,l]) + 1)/2 * emb[b,l,d]
//
// R9: two-phase warp structure.
//   Phase 1: rec-only pipelined pass computes weights into smem (reg-light,
//            so the prefetch pipeline fits in 32 regs and really overlaps).
//   Phase 2: emb-only pure gather-stream with known weights: no shuffles,
//            4 rows/iter front-batched, 2 independent accumulators.
//   __launch_bounds__(256,8) pins regs<=32 -> ~8 CTAs/SM occupancy.

#define TAHE_B 4096
#define TAHE_L 200
#define TAHE_D 128
#define WARPS_PER_CTA 8
#define ROWS_PER_CTA  4        // batch rows per CTA (2 warps each)
#define L_HALF        100      // L per warp

__global__ __launch_bounds__(WARPS_PER_CTA * 32, 8)
void tahe_kernel(const float* __restrict__ rec,
                 const float* __restrict__ cur,
                 const int*   __restrict__ ts,
                 const float* __restrict__ emb,
                 float*       __restrict__ out) {
    __shared__ short s_list[WARPS_PER_CTA][L_HALF + 8];
    __shared__ float s_w   [WARPS_PER_CTA][L_HALF + 8];
    __shared__ float s_part[ROWS_PER_CTA][TAHE_D];   // partials from half==1 warps

    const int warp = threadIdx.x >> 5;
    const int lane = threadIdx.x & 31;
    const int row  = warp >> 1;              // 0..3 within CTA
    const int half = warp & 1;               // which L half
    const int b    = blockIdx.x * ROWS_PER_CTA + row;

    const unsigned lanemask_lt = (1u << lane) - 1u;

    // ---- normalize current representation (lane owns 4 contiguous floats) ----
    float4 c = reinterpret_cast<const float4*>(cur + (size_t)b * TAHE_D)[lane];
    float csq = c.x * c.x + c.y * c.y + c.z * c.z + c.w * c.w;
    #pragma unroll
    for (int o = 16; o > 0; o >>= 1)
        csq += __shfl_xor_sync(0xFFFFFFFFu, csq, o);
    const float cinv = rsqrtf(fmaxf(csq, 1e-12f));
    c.x *= cinv; c.y *= cinv; c.z *= cinv; c.w *= cinv;

    // ---- compact active l indices for this warp's L-half into smem ----
    const int* tsb = ts + (size_t)b * TAHE_L + half * L_HALF;
    int cnt = 0;
    #pragma unroll
    for (int chunk = 0; chunk < 4; chunk++) {           // 4*32 = 128 >= 100
        const int li = chunk * 32 + lane;
        const int t  = (li < L_HALF) ? tsb[li] : 0;
        const unsigned ballot = __ballot_sync(0xFFFFFFFFu, t > 0);
        if (t > 0)
            s_list[warp][cnt + __popc(ballot & lanemask_lt)] =
                (short)(half * L_HALF + li);
        cnt += __popc(ballot);
    }
    __syncwarp();

    const float4* recb = reinterpret_cast<const float4*>(rec + (size_t)b * TAHE_L * TAHE_D);
    const float4* embb = reinterpret_cast<const float4*>(emb + (size_t)b * TAHE_L * TAHE_D);

    // ================= Phase 1: weights (rec only, pipelined) =================
    {
        int i = 0;
        if (cnt >= 2) {
            float4 ra = recb[(size_t)s_list[warp][0] * 32 + lane];
            float4 rb = recb[(size_t)s_list[warp][1] * 32 + lane];

            for (;;) {
                float d0 = ra.x*c.x + ra.y*c.y + ra.z*c.z + ra.w*c.w;
                float s0 = ra.x*ra.x + ra.y*ra.y + ra.z*ra.z + ra.w*ra.w;
                float d1 = rb.x*c.x + rb.y*c.y + rb.z*c.z + rb.w*c.w;
                float s1 = rb.x*rb.x + rb.y*rb.y + rb.z*rb.z + rb.w*rb.w;

                // prefetch next pair while the shuffle chain runs
                const int ii = i + 2;
                const bool more = (ii + 2 <= cnt);
                const int n0 = more ? (int)s_list[warp][ii]     : 0;
                const int n1 = more ? (int)s_list[warp][ii + 1] : 0;
                ra = recb[(size_t)n0 * 32 + lane];
                rb = recb[(size_t)n1 * 32 + lane];

                #pragma unroll
                for (int o = 16; o > 0; o >>= 1) {
                    d0 += __shfl_xor_sync(0xFFFFFFFFu, d0, o);
                    s0 += __shfl_xor_sync(0xFFFFFFFFu, s0, o);
                    d1 += __shfl_xor_sync(0xFFFFFFFFu, d1, o);
                    s1 += __shfl_xor_sync(0xFFFFFFFFu, s1, o);
                }

                if (lane == 0) {
                    s_w[warp][i]     = (d0 * rsqrtf(fmaxf(s0, 1e-12f)) + 1.0f) * 0.5f;
                    s_w[warp][i + 1] = (d1 * rsqrtf(fmaxf(s1, 1e-12f)) + 1.0f) * 0.5f;
                }

                i = ii;
                if (!more) break;
            }
        }
        if (cnt & 1) {
            const float4 r0 = recb[(size_t)s_list[warp][cnt - 1] * 32 + lane];
            float d0 = r0.x*c.x + r0.y*c.y + r0.z*c.z + r0.w*c.w;
            float s0 = r0.x*r0.x + r0.y*r0.y + r0.z*r0.z + r0.w*r0.w;
            #pragma unroll
            for (int o = 16; o > 0; o >>= 1) {
                d0 += __shfl_xor_sync(0xFFFFFFFFu, d0, o);
                s0 += __shfl_xor_sync(0xFFFFFFFFu, s0, o);
            }
            if (lane == 0)
                s_w[warp][cnt - 1] = (d0 * rsqrtf(fmaxf(s0, 1e-12f)) + 1.0f) * 0.5f;
        }
    }
    __syncwarp();

    // ================= Phase 2: pooling (emb only, pure stream) ===============
    float4 accA = make_float4(0.f, 0.f, 0.f, 0.f);
    float4 accB = make_float4(0.f, 0.f, 0.f, 0.f);

    int i = 0;
    for (; i + 4 <= cnt; i += 4) {
        const int l0 = s_list[warp][i];
        const int l1 = s_list[warp][i + 1];
        const int l2 = s_list[warp][i + 2];
        const int l3 = s_list[warp][i + 3];
        const float w0 = s_w[warp][i];
        const float w1 = s_w[warp][i + 1];
        const float w2 = s_w[warp][i + 2];
        const float w3 = s_w[warp][i + 3];

        const float4 e0 = embb[(size_t)l0 * 32 + lane];
        const float4 e1 = embb[(size_t)l1 * 32 + lane];
        const float4 e2 = embb[(size_t)l2 * 32 + lane];
        const float4 e3 = embb[(size_t)l3 * 32 + lane];

        accA.x = fmaf(w0, e0.x, fmaf(w1, e1.x, accA.x));
        accA.y = fmaf(w0, e0.y, fmaf(w1, e1.y, accA.y));
        accA.z = fmaf(w0, e0.z, fmaf(w1, e1.z, accA.z));
        accA.w = fmaf(w0, e0.w, fmaf(w1, e1.w, accA.w));
        accB.x = fmaf(w2, e2.x, fmaf(w3, e3.x, accB.x));
        accB.y = fmaf(w2, e2.y, fmaf(w3, e3.y, accB.y));
        accB.z = fmaf(w2, e2.z, fmaf(w3, e3.z, accB.z));
        accB.w = fmaf(w2, e2.w, fmaf(w3, e3.w, accB.w));
    }
    for (; i < cnt; i++) {
        const int l0 = s_list[warp][i];
        const float w0 = s_w[warp][i];
        const float4 e0 = embb[(size_t)l0 * 32 + lane];
        accA.x = fmaf(w0, e0.x, accA.x);
        accA.y = fmaf(w0, e0.y, accA.y);
        accA.z = fmaf(w0, e0.z, accA.z);
        accA.w = fmaf(w0, e0.w, accA.w);
    }
    float4 acc = make_float4(accA.x + accB.x, accA.y + accB.y,
                             accA.z + accB.z, accA.w + accB.w);

    // ---- combine the two half-warps ----
    if (half == 1)
        reinterpret_cast<float4*>(s_part[row])[lane] = acc;
    __syncthreads();
    if (half == 0) {
        const float4 p = reinterpret_cast<const float4*>(s_part[row])[lane];
        acc.x += p.x; acc.y += p.y; acc.z += p.z; acc.w += p.w;
        reinterpret_cast<float4*>(out + (size_t)b * TAHE_D)[lane] = acc;
    }
}

extern "C" void kernel_launch(void* const* d_in, const int* in_sizes, int n_in,
                              void* d_out, int out_size) {
    const float* rec = (const float*)d_in[0];
    const float* cur = (const float*)d_in[1];
    const int*   ts  = (const int*)  d_in[2];
    const float* emb = (const float*)d_in[3];
    float*       out = (float*)d_out;

    const int ctas = TAHE_B / ROWS_PER_CTA;  // 1024
    tahe_kernel<<<ctas, WARPS_PER_CTA * 32>>>(rec, cur, ts, emb, out);
}

// round 11
// speedup vs baseline: 1.0814x; 1.0434x over previous
#include <cuda_runtime.h>

// TAHE: masked cosine-similarity weighted pooling.
// out[b,d] = sum_l [ts[b,l]>0] * (dot(cur_n[b], rec_n[b,l]) + 1)/2 * emb[b,l,d]
//
// R10: R9 two-phase body, plus:
//   - __ldcs streaming loads for rec/emb (zero-reuse data; evict-first
//     keeps L2 clean and raises pure-stream throughput)
//   - 128-thread CTAs (2 batch rows x 2 warps), grid=2048: finer wave
//     granularity halves the 7-vs-6 CTA/SM tail imbalance of grid=1024.

#define TAHE_B 4096
#define TAHE_L 200
#define TAHE_D 128
#define WARPS_PER_CTA 4
#define ROWS_PER_CTA  2        // batch rows per CTA (2 warps each)
#define L_HALF        100      // L per warp

__global__ __launch_bounds__(WARPS_PER_CTA * 32, 16)
void tahe_kernel(const float* __restrict__ rec,
                 const float* __restrict__ cur,
                 const int*   __restrict__ ts,
                 const float* __restrict__ emb,
                 float*       __restrict__ out) {
    __shared__ short s_list[WARPS_PER_CTA][L_HALF + 8];
    __shared__ float s_w   [WARPS_PER_CTA][L_HALF + 8];
    __shared__ float s_part[ROWS_PER_CTA][TAHE_D];   // partials from half==1 warps

    const int warp = threadIdx.x >> 5;
    const int lane = threadIdx.x & 31;
    const int row  = warp >> 1;              // 0..1 within CTA
    const int half = warp & 1;               // which L half
    const int b    = blockIdx.x * ROWS_PER_CTA + row;

    const unsigned lanemask_lt = (1u << lane) - 1u;

    // ---- normalize current representation (lane owns 4 contiguous floats) ----
    float4 c = reinterpret_cast<const float4*>(cur + (size_t)b * TAHE_D)[lane];
    float csq = c.x * c.x + c.y * c.y + c.z * c.z + c.w * c.w;
    #pragma unroll
    for (int o = 16; o > 0; o >>= 1)
        csq += __shfl_xor_sync(0xFFFFFFFFu, csq, o);
    const float cinv = rsqrtf(fmaxf(csq, 1e-12f));
    c.x *= cinv; c.y *= cinv; c.z *= cinv; c.w *= cinv;

    // ---- compact active l indices for this warp's L-half into smem ----
    const int* tsb = ts + (size_t)b * TAHE_L + half * L_HALF;
    int cnt = 0;
    #pragma unroll
    for (int chunk = 0; chunk < 4; chunk++) {           // 4*32 = 128 >= 100
        const int li = chunk * 32 + lane;
        const int t  = (li < L_HALF) ? tsb[li] : 0;
        const unsigned ballot = __ballot_sync(0xFFFFFFFFu, t > 0);
        if (t > 0)
            s_list[warp][cnt + __popc(ballot & lanemask_lt)] =
                (short)(half * L_HALF + li);
        cnt += __popc(ballot);
    }
    __syncwarp();

    const float4* recb = reinterpret_cast<const float4*>(rec + (size_t)b * TAHE_L * TAHE_D);
    const float4* embb = reinterpret_cast<const float4*>(emb + (size_t)b * TAHE_L * TAHE_D);

    // ================= Phase 1: weights (rec only, pipelined) =================
    {
        int i = 0;
        if (cnt >= 2) {
            float4 ra = __ldcs(&recb[(size_t)s_list[warp][0] * 32 + lane]);
            float4 rb = __ldcs(&recb[(size_t)s_list[warp][1] * 32 + lane]);

            for (;;) {
                float d0 = ra.x*c.x + ra.y*c.y + ra.z*c.z + ra.w*c.w;
                float s0 = ra.x*ra.x + ra.y*ra.y + ra.z*ra.z + ra.w*ra.w;
                float d1 = rb.x*c.x + rb.y*c.y + rb.z*c.z + rb.w*c.w;
                float s1 = rb.x*rb.x + rb.y*rb.y + rb.z*rb.z + rb.w*rb.w;

                // prefetch next pair while the shuffle chain runs
                const int ii = i + 2;
                const bool more = (ii + 2 <= cnt);
                const int n0 = more ? (int)s_list[warp][ii]     : 0;
                const int n1 = more ? (int)s_list[warp][ii + 1] : 0;
                ra = __ldcs(&recb[(size_t)n0 * 32 + lane]);
                rb = __ldcs(&recb[(size_t)n1 * 32 + lane]);

                #pragma unroll
                for (int o = 16; o > 0; o >>= 1) {
                    d0 += __shfl_xor_sync(0xFFFFFFFFu, d0, o);
                    s0 += __shfl_xor_sync(0xFFFFFFFFu, s0, o);
                    d1 += __shfl_xor_sync(0xFFFFFFFFu, d1, o);
                    s1 += __shfl_xor_sync(0xFFFFFFFFu, s1, o);
                }

                if (lane == 0) {
                    s_w[warp][i]     = (d0 * rsqrtf(fmaxf(s0, 1e-12f)) + 1.0f) * 0.5f;
                    s_w[warp][i + 1] = (d1 * rsqrtf(fmaxf(s1, 1e-12f)) + 1.0f) * 0.5f;
                }

                i = ii;
                if (!more) break;
            }
        }
        if (cnt & 1) {
            const float4 r0 = __ldcs(&recb[(size_t)s_list[warp][cnt - 1] * 32 + lane]);
            float d0 = r0.x*c.x + r0.y*c.y + r0.z*c.z + r0.w*c.w;
            float s0 = r0.x*r0.x + r0.y*r0.y + r0.z*r0.z + r0.w*r0.w;
            #pragma unroll
            for (int o = 16; o > 0; o >>= 1) {
                d0 += __shfl_xor_sync(0xFFFFFFFFu, d0, o);
                s0 += __shfl_xor_sync(0xFFFFFFFFu, s0, o);
            }
            if (lane == 0)
                s_w[warp][cnt - 1] = (d0 * rsqrtf(fmaxf(s0, 1e-12f)) + 1.0f) * 0.5f;
        }
    }
    __syncwarp();

    // ================= Phase 2: pooling (emb only, pure stream) ===============
    float4 accA = make_float4(0.f, 0.f, 0.f, 0.f);
    float4 accB = make_float4(0.f, 0.f, 0.f, 0.f);

    int i = 0;
    for (; i + 4 <= cnt; i += 4) {
        const int l0 = s_list[warp][i];
        const int l1 = s_list[warp][i + 1];
        const int l2 = s_list[warp][i + 2];
        const int l3 = s_list[warp][i + 3];
        const float w0 = s_w[warp][i];
        const float w1 = s_w[warp][i + 1];
        const float w2 = s_w[warp][i + 2];
        const float w3 = s_w[warp][i + 3];

        const float4 e0 = __ldcs(&embb[(size_t)l0 * 32 + lane]);
        const float4 e1 = __ldcs(&embb[(size_t)l1 * 32 + lane]);
        const float4 e2 = __ldcs(&embb[(size_t)l2 * 32 + lane]);
        const float4 e3 = __ldcs(&embb[(size_t)l3 * 32 + lane]);

        accA.x = fmaf(w0, e0.x, fmaf(w1, e1.x, accA.x));
        accA.y = fmaf(w0, e0.y, fmaf(w1, e1.y, accA.y));
        accA.z = fmaf(w0, e0.z, fmaf(w1, e1.z, accA.z));
        accA.w = fmaf(w0, e0.w, fmaf(w1, e1.w, accA.w));
        accB.x = fmaf(w2, e2.x, fmaf(w3, e3.x, accB.x));
        accB.y = fmaf(w2, e2.y, fmaf(w3, e3.y, accB.y));
        accB.z = fmaf(w2, e2.z, fmaf(w3, e3.z, accB.z));
        accB.w = fmaf(w2, e2.w, fmaf(w3, e3.w, accB.w));
    }
    for (; i < cnt; i++) {
        const int l0 = s_list[warp][i];
        const float w0 = s_w[warp][i];
        const float4 e0 = __ldcs(&embb[(size_t)l0 * 32 + lane]);
        accA.x = fmaf(w0, e0.x, accA.x);
        accA.y = fmaf(w0, e0.y, accA.y);
        accA.z = fmaf(w0, e0.z, accA.z);
        accA.w = fmaf(w0, e0.w, accA.w);
    }
    float4 acc = make_float4(accA.x + accB.x, accA.y + accB.y,
                             accA.z + accB.z, accA.w + accB.w);

    // ---- combine the two half-warps ----
    if (half == 1)
        reinterpret_cast<float4*>(s_part[row])[lane] = acc;
    __syncthreads();
    if (half == 0) {
        const float4 p = reinterpret_cast<const float4*>(s_part[row])[lane];
        acc.x += p.x; acc.y += p.y; acc.z += p.z; acc.w += p.w;
        reinterpret_cast<float4*>(out + (size_t)b * TAHE_D)[lane] = acc;
    }
}

extern "C" void kernel_launch(void* const* d_in, const int* in_sizes, int n_in,
                              void* d_out, int out_size) {
    const float* rec = (const float*)d_in[0];
    const float* cur = (const float*)d_in[1];
    const int*   ts  = (const int*)  d_in[2];
    const float* emb = (const float*)d_in[3];
    float*       out = (float*)d_out;

    const int ctas = TAHE_B / ROWS_PER_CTA;  // 2048
    tahe_kernel<<<ctas, WARPS_PER_CTA * 32>>>(rec, cur, ts, emb, out);
}